// round 12
// baseline (speedup 1.0000x reference)
#include <cuda_runtime.h>
#include <cstdint>

#define T_LEN   2097152
#define KK      8
#define DD      4
#define CHUNK   64
#define NCHUNK  32768           // CHUNK*NCHUNK >= T_LEN-1
#define NGRP    16384           // 8-lane groups; chain A: g, chain B: g+NGRP
#define WARM_CLEAN 16
#define WARM_QUANT 24
#define WFRAC   0.375f          // WARM_QUANT / CHUNK

#define LOG_2PI_F 1.8378770664093453f

// ---------------- device scratch ----------------
__device__ float g_ltr[64];      // fp32 log-softmax transition (row i, col j at i*8+j)
__device__ float g_lpi[KK];
__device__ float g_ca[KK];
__device__ float g_cb[KK*DD];
__device__ float g_cg[KK*DD];
__device__ float g_SA[NCHUNK];   // clean per-chunk scale sums
__device__ float g_SB[NCHUNK];   // quantized per-chunk scale sums
__device__ float g_P[NCHUNK];    // exclusive prefix of g_SA
__device__ float g_dfin[KK];     // final relative state

// ---------------- setup ----------------
__global__ void hmm_setup(const float* __restrict__ tr,
                          const float* __restrict__ pi,
                          const float* __restrict__ means,
                          const float* __restrict__ log_std)
{
    int i = threadIdx.x;
    if (i < KK) {
        float r[KK]; float m = -1e30f;
        #pragma unroll
        for (int jj = 0; jj < KK; jj++) { r[jj] = tr[i*KK+jj]; m = fmaxf(m, r[jj]); }
        float s = 0.f;
        #pragma unroll
        for (int jj = 0; jj < KK; jj++) s += expf(r[jj] - m);
        float ls = logf(s);
        #pragma unroll
        for (int jj = 0; jj < KK; jj++) g_ltr[i*KK+jj] = (r[jj] - m) - ls;

        float a = 0.f;
        #pragma unroll
        for (int dd = 0; dd < DD; dd++) {
            float lsd = log_std[i*DD+dd];
            float iv  = expf(-2.0f * lsd);
            float mu  = means[i*DD+dd];
            a += -0.5f*LOG_2PI_F - lsd - 0.5f*mu*mu*iv;
            g_cb[i*DD+dd] = mu*iv;
            g_cg[i*DD+dd] = -0.5f*iv;
        }
        g_ca[i] = a;
    } else if (i == KK) {
        float r[KK]; float m = -1e30f;
        #pragma unroll
        for (int jj = 0; jj < KK; jj++) { r[jj] = pi[jj]; m = fmaxf(m, r[jj]); }
        float s = 0.f;
        #pragma unroll
        for (int jj = 0; jj < KK; jj++) s += expf(r[jj] - m);
        float ls = logf(s);
        #pragma unroll
        for (int jj = 0; jj < KK; jj++) g_lpi[jj] = (r[jj] - m) - ls;
    }
}

// grid constants for binade exponent e (|alpha| in [2^e, 2^{e+1}))
__device__ __forceinline__ void setgrid(int e, float& C, float& thresh,
                                        float E[8], const float ltrc[8])
{
    thresh = __int_as_float((e + 128) << 23);                     // 2^{e+1}
    C = (e >= 8) ? 1.5f * __int_as_float((e + 127) << 23) : 0.f;  // 1.5*2^e
    #pragma unroll
    for (int i = 0; i < 8; i++) {
        float q = __fadd_rn(__fadd_rn(ltrc[i], C), -C);           // rnd_u(ltr) (RNE)
        E[i] = expf(q);
    }
}

// ---------------- main pass kernel, 2 chains per 8-lane group ----------------
template<int QUANT>
__global__ __launch_bounds__(256) void hmm_pass(const float* __restrict__ x)
{
    const int lane  = threadIdx.x & 31;
    const int j     = lane & 7;
    const int base  = lane & 24;
    const unsigned gm = 0xFFu << base;
    const int g     = (((blockIdx.x * blockDim.x + threadIdx.x) >> 5) << 2) + (lane >> 3);
    const int cA = g, cB = g + NGRP;

    float ltrc[8];
    #pragma unroll
    for (int i = 0; i < 8; i++) ltrc[i] = g_ltr[i*8 + j];   // column j
    const float cca = g_ca[j];
    const float cb0 = g_cb[j*4+0], cb1 = g_cb[j*4+1], cb2 = g_cb[j*4+2], cb3 = g_cb[j*4+3];
    const float cg0 = g_cg[j*4+0], cg1 = g_cg[j*4+1], cg2 = g_cg[j*4+2], cg3 = g_cg[j*4+3];

    const int WARM = QUANT ? WARM_QUANT : WARM_CLEAN;
    const int tbA = 1 + cA * CHUNK;
    const int tbB = 1 + cB * CHUNK;
    const float4* xp = reinterpret_cast<const float4*>(x);

    float dA, dB, SA = 0.f, SB = 0.f, curA = -1.f, curB = -1.f;
    const bool wA = (cA != 0);

    if (!wA) {
        // exact alpha0 = log_pi + log_em[0]
        float4 x0 = xp[0];
        float p = cca;
        p = fmaf(x0.x, fmaf(cg0, x0.x, cb0), p);
        p = fmaf(x0.y, fmaf(cg1, x0.y, cb1), p);
        p = fmaf(x0.z, fmaf(cg2, x0.z, cb2), p);
        p = fmaf(x0.w, fmaf(cg3, x0.w, cb3), p);
        float a0 = g_lpi[j] + p;
        float a00 = __shfl_sync(gm, a0, base);
        dA = a0 - a00;
        SA = a00;
        curA = a00;
    } else {
        dA = 0.f;
        if (QUANT) curA = g_P[cA] - WFRAC * g_SA[cA-1];
    }
    dB = 0.f;
    if (QUANT) curB = g_P[cB] - WFRAC * g_SA[cB-1];

    float CA, CB, thA, thB, EA[8], EB[8];
    if (QUANT) {
        int eA = (__float_as_int(fmaxf(fabsf(curA), 1.0f)) >> 23) - 127;
        int eB = (__float_as_int(fmaxf(fabsf(curB), 1.0f)) >> 23) - 127;
        setgrid(eA, CA, thA, EA, ltrc);
        setgrid(eB, CB, thB, EB, ltrc);
    } else {
        CA = CB = 0.f; thA = thB = 3.0e38f;
        #pragma unroll
        for (int i = 0; i < 8; i++) { EA[i] = expf(ltrc[i]); EB[i] = EA[i]; }
    }

#define HMM_STEP(d_, S_, cur_, C_, th_, E_, tt, COMMIT, ACCUM)                \
    {                                                                         \
        float4 xv = xp[tt];                                                   \
        float p = cca;                                                        \
        p = fmaf(xv.x, fmaf(cg0, xv.x, cb0), p);                              \
        p = fmaf(xv.y, fmaf(cg1, xv.y, cb1), p);                              \
        p = fmaf(xv.z, fmaf(cg2, xv.z, cb2), p);                              \
        p = fmaf(xv.w, fmaf(cg3, xv.w, cb3), p);                              \
        float em = QUANT ? __fadd_rn(__fadd_rn(p, C_), -C_) : p;              \
        float w = __expf(d_);                                                 \
        float wi, acc;                                                        \
        wi = __shfl_sync(gm, w, base + 0); acc = wi * E_[0];                  \
        wi = __shfl_sync(gm, w, base + 1); acc = fmaf(wi, E_[1], acc);        \
        wi = __shfl_sync(gm, w, base + 2); acc = fmaf(wi, E_[2], acc);        \
        wi = __shfl_sync(gm, w, base + 3); acc = fmaf(wi, E_[3], acc);        \
        wi = __shfl_sync(gm, w, base + 4); acc = fmaf(wi, E_[4], acc);        \
        wi = __shfl_sync(gm, w, base + 5); acc = fmaf(wi, E_[5], acc);        \
        wi = __shfl_sync(gm, w, base + 6); acc = fmaf(wi, E_[6], acc);        \
        wi = __shfl_sync(gm, w, base + 7); acc = fmaf(wi, E_[7], acc);        \
        float L = __logf(acc);                                                \
        float lse = QUANT ? __fadd_rn(__fadd_rn(L, C_), -C_) : L;             \
        float av = lse + em;                                                  \
        float av0 = __shfl_sync(gm, av, base);                                \
        if (COMMIT) {                                                         \
            d_ = av - av0;                                                    \
            if (ACCUM) S_ += av0;                                             \
            if (QUANT) {                                                      \
                cur_ += av0;                                                  \
                if (fabsf(cur_) >= th_) {                                     \
                    int e2 = (__float_as_int(fabsf(cur_)) >> 23) - 127;       \
                    setgrid(e2, C_, th_, E_, ltrc);                           \
                }                                                             \
            }                                                                 \
        }                                                                     \
    }

    // warm-up (chunk 0's chain A executes but never commits)
    #pragma unroll 1
    for (int k = 0; k < WARM; k++) {
        int tA = wA ? (tbA - WARM + k) : 0;
        int tB = tbB - WARM + k;
        HMM_STEP(dA, SA, curA, CA, thA, EA, tA, wA, false)
        HMM_STEP(dB, SB, curB, CB, thB, EB, tB, true, false)
    }
    // main accumulating region
    #pragma unroll 1
    for (int k = 0; k < CHUNK; k++) {
        int tA = tbA + k;                       // always < T_LEN for cA < NGRP
        int tB = tbB + k;
        bool vB = (tB < T_LEN);
        int tBc = vB ? tB : (T_LEN - 1);
        HMM_STEP(dA, SA, curA, CA, thA, EA, tA, true, true)
        HMM_STEP(dB, SB, curB, CB, thB, EB, tBc, vB, vB)
    }
#undef HMM_STEP

    if (j == 0) {
        if (QUANT) { g_SB[cA] = SA; g_SB[cB] = SB; }
        else       { g_SA[cA] = SA; g_SA[cB] = SB; }
    }
    if (QUANT && cB == NCHUNK - 1) g_dfin[j] = dB;
}

// ---------------- exclusive prefix of g_SA -> g_P ----------------
__global__ void hmm_prefix()
{
    __shared__ double sh[1024];
    const int tid = threadIdx.x;       // 1024 threads, 32 chunks each
    const int cpt = NCHUNK / 1024;     // 32
    double s = 0.0;
    for (int k = 0; k < cpt; k++) s += (double)g_SA[tid*cpt + k];
    sh[tid] = s;
    __syncthreads();
    for (int off = 1; off < 1024; off <<= 1) {
        double t = (tid >= off) ? sh[tid - off] : 0.0;
        __syncthreads();
        sh[tid] += t;
        __syncthreads();
    }
    double pre = sh[tid] - s;          // exclusive prefix of this thread's segment
    for (int k = 0; k < cpt; k++) {
        g_P[tid*cpt + k] = (float)pre;
        pre += (double)g_SA[tid*cpt + k];
    }
}

// ---------------- final reduce ----------------
__global__ void hmm_final(float* __restrict__ out)
{
    __shared__ double sh[256];
    const int tid = threadIdx.x;       // 256
    double s = 0.0;
    for (int k = tid; k < NCHUNK; k += 256) s += (double)g_SB[k];
    sh[tid] = s;
    __syncthreads();
    for (int off = 128; off > 0; off >>= 1) {
        if (tid < off) sh[tid] += sh[tid + off];
        __syncthreads();
    }
    if (tid == 0) {
        float m = -1e30f;
        #pragma unroll
        for (int i = 0; i < 8; i++) m = fmaxf(m, g_dfin[i]);
        double acc = 0.0;
        #pragma unroll
        for (int i = 0; i < 8; i++) acc += exp((double)(g_dfin[i] - m));
        out[0] = (float)(sh[0] + (double)m + log(acc));
    }
}

// ---------------- launch ----------------
extern "C" void kernel_launch(void* const* d_in, const int* in_sizes, int n_in,
                              void* d_out, int out_size)
{
    const float* x_seq   = (const float*)d_in[0];
    const float* untrans = (const float*)d_in[1];
    const float* unpi    = (const float*)d_in[2];
    const float* means   = (const float*)d_in[3];
    const float* log_std = (const float*)d_in[4];
    float* out = (float*)d_out;

    hmm_setup<<<1, 32>>>(untrans, unpi, means, log_std);
    hmm_pass<0><<<NGRP/32, 256>>>(x_seq);     // clean pass -> g_SA
    hmm_prefix<<<1, 1024>>>();                // g_SA -> g_P
    hmm_pass<1><<<NGRP/32, 256>>>(x_seq);     // quantized emulation -> g_SB, g_dfin
    hmm_final<<<1, 256>>>(out);
}

// round 14
// speedup vs baseline: 1.5282x; 1.5282x over previous
#include <cuda_runtime.h>
#include <cstdint>

#define T_LEN   2097152
#define KK      8
#define DD      4
#define CHUNK   56
#define NCHUNK  37888           // CHUNK*NCHUNK = 2121728 >= T_LEN-1
#define NGRP    18944           // 8-lane groups; chain A: g, chain B: g+NGRP
#define NBLK    592             // NGRP/32 -> exactly 4 blocks/SM on 148 SMs
#define WARM    24
#define NSAMP   2048
#define SAMP_ACC 64
#define SAMP_WARM 16

#define LOG_2PI_F 1.8378770664093453f

// ---------------- device scratch ----------------
__device__ float g_ltr[64];      // fp32 log-softmax transition (row i, col j at i*8+j)
__device__ float g_lpi[KK];
__device__ float g_ca[KK];
__device__ float g_cb[KK*DD];
__device__ float g_cg[KK*DD];
__device__ float g_msum;         // sum of sampled window scale sums
__device__ float g_SB[NCHUNK];   // quantized per-chunk scale sums
__device__ float g_dfin[KK];     // final relative state

// ---------------- setup ----------------
__global__ void hmm_setup(const float* __restrict__ tr,
                          const float* __restrict__ pi,
                          const float* __restrict__ means,
                          const float* __restrict__ log_std)
{
    int i = threadIdx.x;
    if (i < KK) {
        float r[KK]; float m = -1e30f;
        #pragma unroll
        for (int jj = 0; jj < KK; jj++) { r[jj] = tr[i*KK+jj]; m = fmaxf(m, r[jj]); }
        float s = 0.f;
        #pragma unroll
        for (int jj = 0; jj < KK; jj++) s += expf(r[jj] - m);
        float ls = logf(s);
        #pragma unroll
        for (int jj = 0; jj < KK; jj++) g_ltr[i*KK+jj] = (r[jj] - m) - ls;

        float a = 0.f;
        #pragma unroll
        for (int dd = 0; dd < DD; dd++) {
            float lsd = log_std[i*DD+dd];
            float iv  = expf(-2.0f * lsd);
            float mu  = means[i*DD+dd];
            a += -0.5f*LOG_2PI_F - lsd - 0.5f*mu*mu*iv;
            g_cb[i*DD+dd] = mu*iv;
            g_cg[i*DD+dd] = -0.5f*iv;
        }
        g_ca[i] = a;
    } else if (i == KK) {
        float r[KK]; float m = -1e30f;
        #pragma unroll
        for (int jj = 0; jj < KK; jj++) { r[jj] = pi[jj]; m = fmaxf(m, r[jj]); }
        float s = 0.f;
        #pragma unroll
        for (int jj = 0; jj < KK; jj++) s += expf(r[jj] - m);
        float ls = logf(s);
        #pragma unroll
        for (int jj = 0; jj < KK; jj++) g_lpi[jj] = (r[jj] - m) - ls;
    } else if (i == KK + 1) {
        g_msum = 0.f;
    }
}

// grid constants for binade exponent e (|alpha| in [2^e, 2^{e+1}))
__device__ __forceinline__ void setgrid(int e, float& C, float& thresh,
                                        float E[8], const float ltrc[8])
{
    thresh = __int_as_float((e + 128) << 23);                     // 2^{e+1}
    C = (e >= 8) ? 1.5f * __int_as_float((e + 127) << 23) : 0.f;  // 1.5*2^e
    #pragma unroll
    for (int i = 0; i < 8; i++) {
        float q = __fadd_rn(__fadd_rn(ltrc[i], C), -C);           // rnd_u(ltr) (RNE)
        E[i] = expf(q);
    }
}

// ---------------- sampling pass: estimate mean per-step scale m_bar ----------------
__global__ __launch_bounds__(256) void hmm_sample(const float* __restrict__ x)
{
    const int lane  = threadIdx.x & 31;
    const int j     = lane & 7;
    const int base  = lane & 24;
    const unsigned gm = 0xFFu << base;
    const int g     = (((blockIdx.x * blockDim.x + threadIdx.x) >> 5) << 2) + (lane >> 3);

    float ltrc[8];
    #pragma unroll
    for (int i = 0; i < 8; i++) ltrc[i] = g_ltr[i*8 + j];
    const float cca = g_ca[j];
    const float cb0 = g_cb[j*4+0], cb1 = g_cb[j*4+1], cb2 = g_cb[j*4+2], cb3 = g_cb[j*4+3];
    const float cg0 = g_cg[j*4+0], cg1 = g_cg[j*4+1], cg2 = g_cg[j*4+2], cg3 = g_cg[j*4+3];

    float E[8];
    #pragma unroll
    for (int i = 0; i < 8; i++) E[i] = expf(ltrc[i]);

    const float4* xp = reinterpret_cast<const float4*>(x);
    const int t0 = SAMP_WARM + 1 + g * 1023;     // windows spread over the sequence
    float d = 0.f, S = 0.f;

    #pragma unroll 1
    for (int k = 0; k < SAMP_WARM + SAMP_ACC; k++) {
        int tt = t0 - SAMP_WARM + k;
        float4 xv = xp[tt];
        float p = cca;
        p = fmaf(xv.x, fmaf(cg0, xv.x, cb0), p);
        p = fmaf(xv.y, fmaf(cg1, xv.y, cb1), p);
        p = fmaf(xv.z, fmaf(cg2, xv.z, cb2), p);
        p = fmaf(xv.w, fmaf(cg3, xv.w, cb3), p);
        float w = __expf(d);
        float wi, acc;
        wi = __shfl_sync(gm, w, base + 0); acc = wi * E[0];
        wi = __shfl_sync(gm, w, base + 1); acc = fmaf(wi, E[1], acc);
        wi = __shfl_sync(gm, w, base + 2); acc = fmaf(wi, E[2], acc);
        wi = __shfl_sync(gm, w, base + 3); acc = fmaf(wi, E[3], acc);
        wi = __shfl_sync(gm, w, base + 4); acc = fmaf(wi, E[4], acc);
        wi = __shfl_sync(gm, w, base + 5); acc = fmaf(wi, E[5], acc);
        wi = __shfl_sync(gm, w, base + 6); acc = fmaf(wi, E[6], acc);
        wi = __shfl_sync(gm, w, base + 7); acc = fmaf(wi, E[7], acc);
        float av = __logf(acc) + p;
        float av0 = __shfl_sync(gm, av, base);
        d = av - av0;
        if (k >= SAMP_WARM) S += av0;
    }
    if (j == 0) atomicAdd(&g_msum, S);
}

// ---------------- main quantized pass, 2 chains per 8-lane group ----------------
__global__ __launch_bounds__(256) void hmm_quant(const float* __restrict__ x)
{
    const int lane  = threadIdx.x & 31;
    const int j     = lane & 7;
    const int base  = lane & 24;
    const unsigned gm = 0xFFu << base;
    const int g     = (((blockIdx.x * blockDim.x + threadIdx.x) >> 5) << 2) + (lane >> 3);
    const int cA = g, cB = g + NGRP;

    float ltrc[8];
    #pragma unroll
    for (int i = 0; i < 8; i++) ltrc[i] = g_ltr[i*8 + j];
    const float cca = g_ca[j];
    const float cb0 = g_cb[j*4+0], cb1 = g_cb[j*4+1], cb2 = g_cb[j*4+2], cb3 = g_cb[j*4+3];
    const float cg0 = g_cg[j*4+0], cg1 = g_cg[j*4+1], cg2 = g_cg[j*4+2], cg3 = g_cg[j*4+3];

    const float mbar = g_msum * (1.0f / (float)(NSAMP * SAMP_ACC));
    const int tbA = 1 + cA * CHUNK;
    const int tbB = 1 + cB * CHUNK;
    const float4* xp = reinterpret_cast<const float4*>(x);

    float dA, dB, SA = 0.f, SB = 0.f, curA, curB;
    const bool wA = (cA != 0);

    if (!wA) {
        // exact alpha0 = log_pi + log_em[0]
        float4 x0 = xp[0];
        float p = cca;
        p = fmaf(x0.x, fmaf(cg0, x0.x, cb0), p);
        p = fmaf(x0.y, fmaf(cg1, x0.y, cb1), p);
        p = fmaf(x0.z, fmaf(cg2, x0.z, cb2), p);
        p = fmaf(x0.w, fmaf(cg3, x0.w, cb3), p);
        float a0 = g_lpi[j] + p;
        float a00 = __shfl_sync(gm, a0, base);
        dA = a0 - a00;
        SA = a00;
        curA = a00;
    } else {
        dA = 0.f;
        curA = mbar * (float)(tbA - WARM);
    }
    dB = 0.f;
    curB = mbar * (float)(tbB - WARM);

    float CA, CB, thA, thB, EA[8], EB[8];
    {
        int eA = (__float_as_int(fmaxf(fabsf(curA), 1.0f)) >> 23) - 127;
        int eB = (__float_as_int(fmaxf(fabsf(curB), 1.0f)) >> 23) - 127;
        setgrid(eA, CA, thA, EA, ltrc);
        setgrid(eB, CB, thB, EB, ltrc);
    }

#define HMM_STEP(d_, S_, cur_, C_, th_, E_, tt, COMMIT, ACCUM)                \
    {                                                                         \
        float4 xv = xp[tt];                                                   \
        float p = cca;                                                        \
        p = fmaf(xv.x, fmaf(cg0, xv.x, cb0), p);                              \
        p = fmaf(xv.y, fmaf(cg1, xv.y, cb1), p);                              \
        p = fmaf(xv.z, fmaf(cg2, xv.z, cb2), p);                              \
        p = fmaf(xv.w, fmaf(cg3, xv.w, cb3), p);                              \
        float em = __fadd_rn(__fadd_rn(p, C_), -C_);                          \
        float w = __expf(d_);                                                 \
        float wi, acc;                                                        \
        wi = __shfl_sync(gm, w, base + 0); acc = wi * E_[0];                  \
        wi = __shfl_sync(gm, w, base + 1); acc = fmaf(wi, E_[1], acc);        \
        wi = __shfl_sync(gm, w, base + 2); acc = fmaf(wi, E_[2], acc);        \
        wi = __shfl_sync(gm, w, base + 3); acc = fmaf(wi, E_[3], acc);        \
        wi = __shfl_sync(gm, w, base + 4); acc = fmaf(wi, E_[4], acc);        \
        wi = __shfl_sync(gm, w, base + 5); acc = fmaf(wi, E_[5], acc);        \
        wi = __shfl_sync(gm, w, base + 6); acc = fmaf(wi, E_[6], acc);        \
        wi = __shfl_sync(gm, w, base + 7); acc = fmaf(wi, E_[7], acc);        \
        float L = __logf(acc);                                                \
        float lse = __fadd_rn(__fadd_rn(L, C_), -C_);                         \
        float av = lse + em;                                                  \
        float av0 = __shfl_sync(gm, av, base);                                \
        if (COMMIT) {                                                         \
            d_ = av - av0;                                                    \
            if (ACCUM) S_ += av0;                                             \
            cur_ += av0;                                                      \
            if (fabsf(cur_) >= th_) {                                         \
                int e2 = (__float_as_int(fabsf(cur_)) >> 23) - 127;           \
                setgrid(e2, C_, th_, E_, ltrc);                               \
            }                                                                 \
        }                                                                     \
    }

    // warm-up (chunk 0's chain A executes but never commits)
    #pragma unroll 1
    for (int k = 0; k < WARM; k++) {
        int tA = wA ? (tbA - WARM + k) : 0;
        int tB = min(tbB - WARM + k, T_LEN - 1);
        HMM_STEP(dA, SA, curA, CA, thA, EA, tA, wA, false)
        HMM_STEP(dB, SB, curB, CB, thB, EB, tB, true, false)
    }
    // main accumulating region
    #pragma unroll 1
    for (int k = 0; k < CHUNK; k++) {
        int tA = tbA + k;                       // always < T_LEN for cA < NGRP
        int tB = tbB + k;
        bool vB = (tB < T_LEN);
        int tBc = vB ? tB : (T_LEN - 1);
        HMM_STEP(dA, SA, curA, CA, thA, EA, tA, true, true)
        HMM_STEP(dB, SB, curB, CB, thB, EB, tBc, vB, vB)
    }
#undef HMM_STEP

    if (j == 0) { g_SB[cA] = SA; g_SB[cB] = SB; }

    // final relative state lives in the chunk containing t = T_LEN-1
    const int lastc = (T_LEN - 2) / CHUNK;      // chunk index of final step
    if (cB == lastc) g_dfin[j] = dB;
    if (cA == lastc) g_dfin[j] = dA;            // (only one of these matches)
}

// ---------------- final reduce ----------------
__global__ void hmm_final(float* __restrict__ out)
{
    __shared__ double sh[256];
    const int tid = threadIdx.x;       // 256
    double s = 0.0;
    for (int k = tid; k < NCHUNK; k += 256) s += (double)g_SB[k];
    sh[tid] = s;
    __syncthreads();
    for (int off = 128; off > 0; off >>= 1) {
        if (tid < off) sh[tid] += sh[tid + off];
        __syncthreads();
    }
    if (tid == 0) {
        float m = -1e30f;
        #pragma unroll
        for (int i = 0; i < 8; i++) m = fmaxf(m, g_dfin[i]);
        double acc = 0.0;
        #pragma unroll
        for (int i = 0; i < 8; i++) acc += exp((double)(g_dfin[i] - m));
        out[0] = (float)(sh[0] + (double)m + log(acc));
    }
}

// ---------------- launch ----------------
extern "C" void kernel_launch(void* const* d_in, const int* in_sizes, int n_in,
                              void* d_out, int out_size)
{
    const float* x_seq   = (const float*)d_in[0];
    const float* untrans = (const float*)d_in[1];
    const float* unpi    = (const float*)d_in[2];
    const float* means   = (const float*)d_in[3];
    const float* log_std = (const float*)d_in[4];
    float* out = (float*)d_out;

    hmm_setup<<<1, 32>>>(untrans, unpi, means, log_std);
    hmm_sample<<<NSAMP/32, 256>>>(x_seq);     // estimate m_bar -> g_msum
    hmm_quant<<<NBLK, 256>>>(x_seq);          // quantized emulation -> g_SB, g_dfin
    hmm_final<<<1, 256>>>(out);
}

// round 15
// speedup vs baseline: 2.1083x; 1.3796x over previous
#include <cuda_runtime.h>
#include <cstdint>

#define T_LEN   2097152
#define KK      8
#define DD      4
#define CHUNK   56
#define NCHUNK  37888           // CHUNK*NCHUNK = 2121728 >= T_LEN-1
#define NGRP    18944           // 8-lane groups; chain A: g, chain B: g+NGRP
#define NBLK    592             // NGRP/32 -> exactly 4 blocks/SM on 148 SMs
#define WARM    24
#define NSAMP   2048
#define SAMP_ACC 64
#define SAMP_WARM 16

#define LOG_2PI_F 1.8378770664093453f

// ---------------- device scratch ----------------
__device__ float  g_ltr[64];     // fp32 log-softmax transition (row i, col j at i*8+j)
__device__ float  g_lpi[KK];
__device__ float  g_ca[KK];
__device__ float  g_cb[KK*DD];
__device__ float  g_cg[KK*DD];
__device__ float  g_msum;        // sum of sampled window scale sums
__device__ double g_sum;         // accumulated scale sum (atomic)
__device__ float  g_dfin[KK];    // final relative state

// ---------------- setup ----------------
__global__ void hmm_setup(const float* __restrict__ tr,
                          const float* __restrict__ pi,
                          const float* __restrict__ means,
                          const float* __restrict__ log_std)
{
    int i = threadIdx.x;
    if (i < KK) {
        float r[KK]; float m = -1e30f;
        #pragma unroll
        for (int jj = 0; jj < KK; jj++) { r[jj] = tr[i*KK+jj]; m = fmaxf(m, r[jj]); }
        float s = 0.f;
        #pragma unroll
        for (int jj = 0; jj < KK; jj++) s += expf(r[jj] - m);
        float ls = logf(s);
        #pragma unroll
        for (int jj = 0; jj < KK; jj++) g_ltr[i*KK+jj] = (r[jj] - m) - ls;

        float a = 0.f;
        #pragma unroll
        for (int dd = 0; dd < DD; dd++) {
            float lsd = log_std[i*DD+dd];
            float iv  = expf(-2.0f * lsd);
            float mu  = means[i*DD+dd];
            a += -0.5f*LOG_2PI_F - lsd - 0.5f*mu*mu*iv;
            g_cb[i*DD+dd] = mu*iv;
            g_cg[i*DD+dd] = -0.5f*iv;
        }
        g_ca[i] = a;
    } else if (i == KK) {
        float r[KK]; float m = -1e30f;
        #pragma unroll
        for (int jj = 0; jj < KK; jj++) { r[jj] = pi[jj]; m = fmaxf(m, r[jj]); }
        float s = 0.f;
        #pragma unroll
        for (int jj = 0; jj < KK; jj++) s += expf(r[jj] - m);
        float ls = logf(s);
        #pragma unroll
        for (int jj = 0; jj < KK; jj++) g_lpi[jj] = (r[jj] - m) - ls;
    } else if (i == KK + 1) {
        g_msum = 0.f;
        g_sum  = 0.0;
    }
}

// grid constants for binade exponent e (|alpha| in [2^e, 2^{e+1}))
__device__ __forceinline__ void setgrid(int e, float& C, float& thresh,
                                        float E[8], const float ltrc[8])
{
    thresh = __int_as_float((e + 128) << 23);                     // 2^{e+1}
    C = (e >= 8) ? 1.5f * __int_as_float((e + 127) << 23) : 0.f;  // 1.5*2^e
    #pragma unroll
    for (int i = 0; i < 8; i++) {
        float q = __fadd_rn(__fadd_rn(ltrc[i], C), -C);           // rnd_u(ltr) (RNE)
        E[i] = expf(q);
    }
}

// ---------------- sampling pass: estimate mean per-step scale m_bar ----------------
__global__ __launch_bounds__(256) void hmm_sample(const float* __restrict__ x)
{
    const int lane  = threadIdx.x & 31;
    const int j     = lane & 7;
    const int base  = lane & 24;
    const unsigned gm = 0xFFu << base;
    const int g     = (((blockIdx.x * blockDim.x + threadIdx.x) >> 5) << 2) + (lane >> 3);

    float ltrc[8];
    #pragma unroll
    for (int i = 0; i < 8; i++) ltrc[i] = g_ltr[i*8 + j];
    const float cca = g_ca[j];
    const float cb0 = g_cb[j*4+0], cb1 = g_cb[j*4+1], cb2 = g_cb[j*4+2], cb3 = g_cb[j*4+3];
    const float cg0 = g_cg[j*4+0], cg1 = g_cg[j*4+1], cg2 = g_cg[j*4+2], cg3 = g_cg[j*4+3];

    float E[8];
    #pragma unroll
    for (int i = 0; i < 8; i++) E[i] = expf(ltrc[i]);

    const float4* xp = reinterpret_cast<const float4*>(x);
    const int t0 = SAMP_WARM + 1 + g * 1023;     // windows spread over the sequence
    float d = 0.f, S = 0.f;

    #pragma unroll 1
    for (int k = 0; k < SAMP_WARM + SAMP_ACC; k++) {
        int tt = t0 - SAMP_WARM + k;
        float4 xv = xp[tt];
        float p = cca;
        p = fmaf(xv.x, fmaf(cg0, xv.x, cb0), p);
        p = fmaf(xv.y, fmaf(cg1, xv.y, cb1), p);
        p = fmaf(xv.z, fmaf(cg2, xv.z, cb2), p);
        p = fmaf(xv.w, fmaf(cg3, xv.w, cb3), p);
        float w = __expf(d);
        float wi, acc;
        wi = __shfl_sync(gm, w, base + 0); acc = wi * E[0];
        wi = __shfl_sync(gm, w, base + 1); acc = fmaf(wi, E[1], acc);
        wi = __shfl_sync(gm, w, base + 2); acc = fmaf(wi, E[2], acc);
        wi = __shfl_sync(gm, w, base + 3); acc = fmaf(wi, E[3], acc);
        wi = __shfl_sync(gm, w, base + 4); acc = fmaf(wi, E[4], acc);
        wi = __shfl_sync(gm, w, base + 5); acc = fmaf(wi, E[5], acc);
        wi = __shfl_sync(gm, w, base + 6); acc = fmaf(wi, E[6], acc);
        wi = __shfl_sync(gm, w, base + 7); acc = fmaf(wi, E[7], acc);
        float av = __logf(acc) + p;
        float av0 = __shfl_sync(gm, av, base);
        d = av - av0;
        if (k >= SAMP_WARM) S += av0;
    }
    if (j == 0) atomicAdd(&g_msum, S);
}

// ---------------- main quantized pass, 2 chains per 8-lane group ----------------
__global__ __launch_bounds__(256) void hmm_quant(const float* __restrict__ x)
{
    const int lane  = threadIdx.x & 31;
    const int j     = lane & 7;
    const int base  = lane & 24;
    const unsigned gm = 0xFFu << base;
    const int warp  = threadIdx.x >> 5;
    const int g     = (((blockIdx.x * blockDim.x + threadIdx.x) >> 5) << 2) + (lane >> 3);
    const int cA = g, cB = g + NGRP;

    __shared__ double sred[32];

    float ltrc[8];
    #pragma unroll
    for (int i = 0; i < 8; i++) ltrc[i] = g_ltr[i*8 + j];
    const float cca = g_ca[j];
    const float cb0 = g_cb[j*4+0], cb1 = g_cb[j*4+1], cb2 = g_cb[j*4+2], cb3 = g_cb[j*4+3];
    const float cg0 = g_cg[j*4+0], cg1 = g_cg[j*4+1], cg2 = g_cg[j*4+2], cg3 = g_cg[j*4+3];

    const float mbar = g_msum * (1.0f / (float)(NSAMP * SAMP_ACC));
    const int tbA = 1 + cA * CHUNK;
    const int tbB = 1 + cB * CHUNK;
    const float4* xp = reinterpret_cast<const float4*>(x);

    float dA, dB, SA = 0.f, SB = 0.f, curA, curB;
    const bool wA = (cA != 0);

    if (!wA) {
        // exact alpha0 = log_pi + log_em[0]
        float4 x0 = xp[0];
        float p = cca;
        p = fmaf(x0.x, fmaf(cg0, x0.x, cb0), p);
        p = fmaf(x0.y, fmaf(cg1, x0.y, cb1), p);
        p = fmaf(x0.z, fmaf(cg2, x0.z, cb2), p);
        p = fmaf(x0.w, fmaf(cg3, x0.w, cb3), p);
        float a0 = g_lpi[j] + p;
        float a00 = __shfl_sync(gm, a0, base);
        dA = a0 - a00;
        SA = a00;
        curA = a00;
    } else {
        dA = 0.f;
        curA = mbar * (float)(tbA - WARM);
    }
    dB = 0.f;
    curB = mbar * (float)(tbB - WARM);

    float CA, CB, thA, thB, EA[8], EB[8];
    {
        int eA = (__float_as_int(fmaxf(fabsf(curA), 1.0f)) >> 23) - 127;
        int eB = (__float_as_int(fmaxf(fabsf(curB), 1.0f)) >> 23) - 127;
        setgrid(eA, CA, thA, EA, ltrc);
        setgrid(eB, CB, thB, EB, ltrc);
    }

#define HMM_STEP(d_, S_, cur_, C_, th_, E_, tt, COMMIT, ACCUM)                \
    {                                                                         \
        float4 xv = xp[tt];                                                   \
        float p = cca;                                                        \
        p = fmaf(xv.x, fmaf(cg0, xv.x, cb0), p);                              \
        p = fmaf(xv.y, fmaf(cg1, xv.y, cb1), p);                              \
        p = fmaf(xv.z, fmaf(cg2, xv.z, cb2), p);                              \
        p = fmaf(xv.w, fmaf(cg3, xv.w, cb3), p);                              \
        float em = __fadd_rn(__fadd_rn(p, C_), -C_);                          \
        float w = __expf(d_);                                                 \
        float wi, acc;                                                        \
        wi = __shfl_sync(gm, w, base + 0); acc = wi * E_[0];                  \
        wi = __shfl_sync(gm, w, base + 1); acc = fmaf(wi, E_[1], acc);        \
        wi = __shfl_sync(gm, w, base + 2); acc = fmaf(wi, E_[2], acc);        \
        wi = __shfl_sync(gm, w, base + 3); acc = fmaf(wi, E_[3], acc);        \
        wi = __shfl_sync(gm, w, base + 4); acc = fmaf(wi, E_[4], acc);        \
        wi = __shfl_sync(gm, w, base + 5); acc = fmaf(wi, E_[5], acc);        \
        wi = __shfl_sync(gm, w, base + 6); acc = fmaf(wi, E_[6], acc);        \
        wi = __shfl_sync(gm, w, base + 7); acc = fmaf(wi, E_[7], acc);        \
        float L = __logf(acc);                                                \
        float lse = __fadd_rn(__fadd_rn(L, C_), -C_);                         \
        float av = lse + em;                                                  \
        float av0 = __shfl_sync(gm, av, base);                                \
        if (COMMIT) {                                                         \
            d_ = av - av0;                                                    \
            if (ACCUM) S_ += av0;                                             \
            cur_ += av0;                                                      \
            if (fabsf(cur_) >= th_) {                                         \
                int e2 = (__float_as_int(fabsf(cur_)) >> 23) - 127;           \
                setgrid(e2, C_, th_, E_, ltrc);                               \
            }                                                                 \
        }                                                                     \
    }

    // warm-up (chunk 0's chain A executes but never commits)
    #pragma unroll 1
    for (int k = 0; k < WARM; k++) {
        int tA = wA ? (tbA - WARM + k) : 0;
        int tB = min(tbB - WARM + k, T_LEN - 1);
        HMM_STEP(dA, SA, curA, CA, thA, EA, tA, wA, false)
        HMM_STEP(dB, SB, curB, CB, thB, EB, tB, true, false)
    }
    // main accumulating region
    #pragma unroll 1
    for (int k = 0; k < CHUNK; k++) {
        int tA = tbA + k;                       // always < T_LEN for cA < NGRP
        int tB = tbB + k;
        bool vB = (tB < T_LEN);
        int tBc = vB ? tB : (T_LEN - 1);
        HMM_STEP(dA, SA, curA, CA, thA, EA, tA, true, true)
        HMM_STEP(dB, SB, curB, CB, thB, EB, tBc, vB, vB)
    }
#undef HMM_STEP

    // ---- in-block reduction of chunk sums, one atomic per block ----
    if (j == 0) sred[warp * 4 + (lane >> 3)] = (double)SA + (double)SB;
    __syncthreads();
    if (threadIdx.x == 0) {
        double t = 0.0;
        #pragma unroll
        for (int q = 0; q < 32; q++) t += sred[q];
        atomicAdd(&g_sum, t);
    }

    // final relative state lives in the chunk containing t = T_LEN-1
    const int lastc = (T_LEN - 2) / CHUNK;      // chunk index of final step
    if (cB == lastc) g_dfin[j] = dB;
    if (cA == lastc) g_dfin[j] = dA;            // (only one of these matches)
}

// ---------------- final: tiny scalar combine ----------------
__global__ void hmm_final(float* __restrict__ out)
{
    if (threadIdx.x == 0) {
        float m = -1e30f;
        #pragma unroll
        for (int i = 0; i < 8; i++) m = fmaxf(m, g_dfin[i]);
        double acc = 0.0;
        #pragma unroll
        for (int i = 0; i < 8; i++) acc += exp((double)(g_dfin[i] - m));
        out[0] = (float)(g_sum + (double)m + log(acc));
    }
}

// ---------------- launch ----------------
extern "C" void kernel_launch(void* const* d_in, const int* in_sizes, int n_in,
                              void* d_out, int out_size)
{
    const float* x_seq   = (const float*)d_in[0];
    const float* untrans = (const float*)d_in[1];
    const float* unpi    = (const float*)d_in[2];
    const float* means   = (const float*)d_in[3];
    const float* log_std = (const float*)d_in[4];
    float* out = (float*)d_out;

    hmm_setup<<<1, 32>>>(untrans, unpi, means, log_std);
    hmm_sample<<<NSAMP/32, 256>>>(x_seq);     // estimate m_bar -> g_msum
    hmm_quant<<<NBLK, 256>>>(x_seq);          // quantized emulation -> g_sum, g_dfin
    hmm_final<<<1, 32>>>(out);
}

// round 16
// speedup vs baseline: 2.2245x; 1.0551x over previous
#include <cuda_runtime.h>
#include <cstdint>

#define T_LEN   2097152
#define KK      8
#define DD      4
#define CHUNK   56
#define NCHUNK  37888           // CHUNK*NCHUNK = 2121728 >= T_LEN-1
#define NGRP    18944           // 8-lane groups; chain A: g, chain B: g+NGRP
#define NBLK    592             // NGRP/32 -> exactly 4 blocks/SM on 148 SMs
#define WARM    24
#define NSAMP   1024
#define SAMP_ACC 64
#define SAMP_WARM 16

#define LOG_2PI_F 1.8378770664093453f

// ---------------- device scratch ----------------
__device__ float  g_ltr[64];     // fp32 log-softmax transition (row i, col j at i*8+j)
__device__ float  g_lpi[KK];
__device__ float  g_ca[KK];
__device__ float  g_cb[KK*DD];
__device__ float  g_cg[KK*DD];
__device__ float  g_msum;        // sum of sampled window scale sums
__device__ double g_sum;         // accumulated scale sum (atomic)
__device__ float  g_dfin[KK];    // final relative state
__device__ unsigned g_done;      // finished-block counter

// ---------------- setup ----------------
__global__ void hmm_setup(const float* __restrict__ tr,
                          const float* __restrict__ pi,
                          const float* __restrict__ means,
                          const float* __restrict__ log_std)
{
    int i = threadIdx.x;
    if (i < KK) {
        float r[KK]; float m = -1e30f;
        #pragma unroll
        for (int jj = 0; jj < KK; jj++) { r[jj] = tr[i*KK+jj]; m = fmaxf(m, r[jj]); }
        float s = 0.f;
        #pragma unroll
        for (int jj = 0; jj < KK; jj++) s += expf(r[jj] - m);
        float ls = logf(s);
        #pragma unroll
        for (int jj = 0; jj < KK; jj++) g_ltr[i*KK+jj] = (r[jj] - m) - ls;

        float a = 0.f;
        #pragma unroll
        for (int dd = 0; dd < DD; dd++) {
            float lsd = log_std[i*DD+dd];
            float iv  = expf(-2.0f * lsd);
            float mu  = means[i*DD+dd];
            a += -0.5f*LOG_2PI_F - lsd - 0.5f*mu*mu*iv;
            g_cb[i*DD+dd] = mu*iv;
            g_cg[i*DD+dd] = -0.5f*iv;
        }
        g_ca[i] = a;
    } else if (i == KK) {
        float r[KK]; float m = -1e30f;
        #pragma unroll
        for (int jj = 0; jj < KK; jj++) { r[jj] = pi[jj]; m = fmaxf(m, r[jj]); }
        float s = 0.f;
        #pragma unroll
        for (int jj = 0; jj < KK; jj++) s += expf(r[jj] - m);
        float ls = logf(s);
        #pragma unroll
        for (int jj = 0; jj < KK; jj++) g_lpi[jj] = (r[jj] - m) - ls;
    } else if (i == KK + 1) {
        g_msum = 0.f;
        g_sum  = 0.0;
        g_done = 0u;
    }
}

// grid constants for binade exponent e (|alpha| in [2^e, 2^{e+1}))
__device__ __forceinline__ void setgrid(int e, float& C, float& thresh,
                                        float E[8], const float ltrc[8])
{
    thresh = __int_as_float((e + 128) << 23);                     // 2^{e+1}
    C = (e >= 8) ? 1.5f * __int_as_float((e + 127) << 23) : 0.f;  // 1.5*2^e
    #pragma unroll
    for (int i = 0; i < 8; i++) {
        float q = __fadd_rn(__fadd_rn(ltrc[i], C), -C);           // rnd_u(ltr) (RNE)
        E[i] = expf(q);
    }
}

// ---------------- sampling pass: estimate mean per-step scale m_bar ----------------
__global__ __launch_bounds__(256) void hmm_sample(const float* __restrict__ x)
{
    const int lane  = threadIdx.x & 31;
    const int j     = lane & 7;
    const int base  = lane & 24;
    const unsigned gm = 0xFFu << base;
    const int g     = (((blockIdx.x * blockDim.x + threadIdx.x) >> 5) << 2) + (lane >> 3);

    float ltrc[8];
    #pragma unroll
    for (int i = 0; i < 8; i++) ltrc[i] = g_ltr[i*8 + j];
    const float cca = g_ca[j];
    const float cb0 = g_cb[j*4+0], cb1 = g_cb[j*4+1], cb2 = g_cb[j*4+2], cb3 = g_cb[j*4+3];
    const float cg0 = g_cg[j*4+0], cg1 = g_cg[j*4+1], cg2 = g_cg[j*4+2], cg3 = g_cg[j*4+3];

    float E[8];
    #pragma unroll
    for (int i = 0; i < 8; i++) E[i] = expf(ltrc[i]);

    const float4* xp = reinterpret_cast<const float4*>(x);
    const int t0 = SAMP_WARM + 1 + g * 2047;     // windows spread over the sequence
    float d = 0.f, S = 0.f;

    #pragma unroll 1
    for (int k = 0; k < SAMP_WARM + SAMP_ACC; k++) {
        int tt = t0 - SAMP_WARM + k;
        float4 xv = xp[tt];
        float p = cca;
        p = fmaf(xv.x, fmaf(cg0, xv.x, cb0), p);
        p = fmaf(xv.y, fmaf(cg1, xv.y, cb1), p);
        p = fmaf(xv.z, fmaf(cg2, xv.z, cb2), p);
        p = fmaf(xv.w, fmaf(cg3, xv.w, cb3), p);
        float w = __expf(d);
        float wi, acc;
        wi = __shfl_sync(gm, w, base + 0); acc = wi * E[0];
        wi = __shfl_sync(gm, w, base + 1); acc = fmaf(wi, E[1], acc);
        wi = __shfl_sync(gm, w, base + 2); acc = fmaf(wi, E[2], acc);
        wi = __shfl_sync(gm, w, base + 3); acc = fmaf(wi, E[3], acc);
        wi = __shfl_sync(gm, w, base + 4); acc = fmaf(wi, E[4], acc);
        wi = __shfl_sync(gm, w, base + 5); acc = fmaf(wi, E[5], acc);
        wi = __shfl_sync(gm, w, base + 6); acc = fmaf(wi, E[6], acc);
        wi = __shfl_sync(gm, w, base + 7); acc = fmaf(wi, E[7], acc);
        float av = __logf(acc) + p;
        float av0 = __shfl_sync(gm, av, base);
        d = av - av0;
        if (k >= SAMP_WARM) S += av0;
    }
    if (j == 0) atomicAdd(&g_msum, S);
}

// ---------------- main quantized pass, 2 chains per 8-lane group ----------------
__global__ __launch_bounds__(256) void hmm_quant(const float* __restrict__ x,
                                                 float* __restrict__ out)
{
    const int lane  = threadIdx.x & 31;
    const int j     = lane & 7;
    const int base  = lane & 24;
    const unsigned gm = 0xFFu << base;
    const int warp  = threadIdx.x >> 5;
    const int g     = (((blockIdx.x * blockDim.x + threadIdx.x) >> 5) << 2) + (lane >> 3);
    const int cA = g, cB = g + NGRP;

    __shared__ double sred[32];

    float ltrc[8];
    #pragma unroll
    for (int i = 0; i < 8; i++) ltrc[i] = g_ltr[i*8 + j];
    const float cca = g_ca[j];
    const float cb0 = g_cb[j*4+0], cb1 = g_cb[j*4+1], cb2 = g_cb[j*4+2], cb3 = g_cb[j*4+3];
    const float cg0 = g_cg[j*4+0], cg1 = g_cg[j*4+1], cg2 = g_cg[j*4+2], cg3 = g_cg[j*4+3];

    const float mbar = g_msum * (1.0f / (float)(NSAMP * SAMP_ACC));
    const int tbA = 1 + cA * CHUNK;
    const int tbB = 1 + cB * CHUNK;
    const float4* xp = reinterpret_cast<const float4*>(x);

    float dA, dB, SA = 0.f, SB = 0.f, curA, curB;
    const bool wA = (cA != 0);

    if (!wA) {
        // exact alpha0 = log_pi + log_em[0]
        float4 x0 = xp[0];
        float p = cca;
        p = fmaf(x0.x, fmaf(cg0, x0.x, cb0), p);
        p = fmaf(x0.y, fmaf(cg1, x0.y, cb1), p);
        p = fmaf(x0.z, fmaf(cg2, x0.z, cb2), p);
        p = fmaf(x0.w, fmaf(cg3, x0.w, cb3), p);
        float a0 = g_lpi[j] + p;
        float a00 = __shfl_sync(gm, a0, base);
        dA = a0 - a00;
        SA = a00;
        curA = a00;
    } else {
        dA = 0.f;
        curA = mbar * (float)(tbA - WARM);
    }
    dB = 0.f;
    curB = mbar * (float)(tbB - WARM);

    float CA, CB, thA, thB, EA[8], EB[8];
    {
        int eA = (__float_as_int(fmaxf(fabsf(curA), 1.0f)) >> 23) - 127;
        int eB = (__float_as_int(fmaxf(fabsf(curB), 1.0f)) >> 23) - 127;
        setgrid(eA, CA, thA, EA, ltrc);
        setgrid(eB, CB, thB, EB, ltrc);
    }

#define HMM_STEP(d_, S_, cur_, C_, th_, E_, tt, COMMIT, ACCUM)                \
    {                                                                         \
        float4 xv = xp[tt];                                                   \
        float p = cca;                                                        \
        p = fmaf(xv.x, fmaf(cg0, xv.x, cb0), p);                              \
        p = fmaf(xv.y, fmaf(cg1, xv.y, cb1), p);                              \
        p = fmaf(xv.z, fmaf(cg2, xv.z, cb2), p);                              \
        p = fmaf(xv.w, fmaf(cg3, xv.w, cb3), p);                              \
        float em = __fadd_rn(__fadd_rn(p, C_), -C_);                          \
        float w = __expf(d_);                                                 \
        float wi, acc;                                                        \
        wi = __shfl_sync(gm, w, base + 0); acc = wi * E_[0];                  \
        wi = __shfl_sync(gm, w, base + 1); acc = fmaf(wi, E_[1], acc);        \
        wi = __shfl_sync(gm, w, base + 2); acc = fmaf(wi, E_[2], acc);        \
        wi = __shfl_sync(gm, w, base + 3); acc = fmaf(wi, E_[3], acc);        \
        wi = __shfl_sync(gm, w, base + 4); acc = fmaf(wi, E_[4], acc);        \
        wi = __shfl_sync(gm, w, base + 5); acc = fmaf(wi, E_[5], acc);        \
        wi = __shfl_sync(gm, w, base + 6); acc = fmaf(wi, E_[6], acc);        \
        wi = __shfl_sync(gm, w, base + 7); acc = fmaf(wi, E_[7], acc);        \
        float L = __logf(acc);                                                \
        float lse = __fadd_rn(__fadd_rn(L, C_), -C_);                         \
        float av = lse + em;                                                  \
        float av0 = __shfl_sync(gm, av, base);                                \
        if (COMMIT) {                                                         \
            d_ = av - av0;                                                    \
            if (ACCUM) S_ += av0;                                             \
            cur_ += av0;                                                      \
            if (fabsf(cur_) >= th_) {                                         \
                int e2 = (__float_as_int(fabsf(cur_)) >> 23) - 127;           \
                setgrid(e2, C_, th_, E_, ltrc);                               \
            }                                                                 \
        }                                                                     \
    }

    // warm-up (chunk 0's chain A executes but never commits)
    #pragma unroll 1
    for (int k = 0; k < WARM; k++) {
        int tA = wA ? (tbA - WARM + k) : 0;
        int tB = min(tbB - WARM + k, T_LEN - 1);
        HMM_STEP(dA, SA, curA, CA, thA, EA, tA, wA, false)
        HMM_STEP(dB, SB, curB, CB, thB, EB, tB, true, false)
    }
    // main accumulating region
    #pragma unroll 1
    for (int k = 0; k < CHUNK; k++) {
        int tA = tbA + k;                       // always < T_LEN for cA < NGRP
        int tB = tbB + k;
        bool vB = (tB < T_LEN);
        int tBc = vB ? tB : (T_LEN - 1);
        HMM_STEP(dA, SA, curA, CA, thA, EA, tA, true, true)
        HMM_STEP(dB, SB, curB, CB, thB, EB, tBc, vB, vB)
    }
#undef HMM_STEP

    // final relative state lives in the chunk containing t = T_LEN-1
    const int lastc = (T_LEN - 2) / CHUNK;      // chunk index of final step
    if (cB == lastc) g_dfin[j] = dB;
    if (cA == lastc) g_dfin[j] = dA;            // (only one of these matches)

    // ---- in-block reduction of chunk sums, one atomic per block ----
    if (j == 0) sred[warp * 4 + (lane >> 3)] = (double)SA + (double)SB;
    __syncthreads();
    if (threadIdx.x == 0) {
        double t = 0.0;
        #pragma unroll
        for (int q = 0; q < 32; q++) t += sred[q];
        atomicAdd(&g_sum, t);
        __threadfence();
        unsigned ticket = atomicAdd(&g_done, 1u);
        if (ticket == NBLK - 1) {
            // all blocks' g_sum/g_dfin contributions are visible
            __threadfence();
            float m = -1e30f;
            #pragma unroll
            for (int i = 0; i < 8; i++) m = fmaxf(m, g_dfin[i]);
            float acc = 0.f;
            #pragma unroll
            for (int i = 0; i < 8; i++) acc += __expf(g_dfin[i] - m);
            double total = g_sum + (double)m + (double)__logf(acc);
            out[0] = (float)total;
        }
    }
}

// ---------------- launch ----------------
extern "C" void kernel_launch(void* const* d_in, const int* in_sizes, int n_in,
                              void* d_out, int out_size)
{
    const float* x_seq   = (const float*)d_in[0];
    const float* untrans = (const float*)d_in[1];
    const float* unpi    = (const float*)d_in[2];
    const float* means   = (const float*)d_in[3];
    const float* log_std = (const float*)d_in[4];
    float* out = (float*)d_out;

    hmm_setup<<<1, 32>>>(untrans, unpi, means, log_std);
    hmm_sample<<<NSAMP/32, 256>>>(x_seq);     // estimate m_bar -> g_msum
    hmm_quant<<<NBLK, 256>>>(x_seq, out);     // quantized emulation -> out
}